// round 10
// baseline (speedup 1.0000x reference)
#include <cuda_runtime.h>
#include <cuda_bf16.h>
#include <math.h>
#include <stdint.h>

typedef __nv_bfloat16 bf16;

// ---------------- Problem constants ----------------
#define D_MODEL 768
#define SEQ     4096
#define BATCH   8
#define TOKENS  (BATCH*SEQ)            // 32768
#define NELEM   (TOKENS*D_MODEL)       // 25165824
#define N1      (2*D_MODEL)            // 1536

// ---------------- Scratch (device globals; no allocation anywhere) ----------------
__device__ __align__(256) bf16 g_xn[NELEM];     // LN output (GEMM0 A)
__device__ __align__(256) bf16 g_x1pre[NELEM];  // pre-conv x1
__device__ __align__(256) bf16 g_sz[NELEM];     // silu(z)
__device__ __align__(256) bf16 g_x1[NELEM];     // post-conv x1 (GEMM1 A)
__device__ __align__(256) bf16 g_y[NELEM];      // yact (GEMM2 A)
__device__ float g_hs[TOKENS];
__device__ float g_a[D_MODEL];
__device__ float g_wB[D_MODEL];
__device__ __align__(256) bf16 g_WinT[N1*D_MODEL];       // W_in^T  [1536,768]
__device__ __align__(256) bf16 g_WxT[D_MODEL*D_MODEL];   // W_x[:,16:784]^T [768,768]
__device__ __align__(256) bf16 g_WoutT[D_MODEL*D_MODEL]; // W_out^T [768,768]

// ---------------- helpers ----------------
__device__ __forceinline__ uint32_t smem_u32(const void* p) {
    uint32_t a;
    asm("{ .reg .u64 t; cvta.to.shared.u64 t, %1; cvt.u32.u64 %0, t; }" : "=r"(a) : "l"(p));
    return a;
}
__device__ __forceinline__ uint32_t pk2(float a, float b) {
    __nv_bfloat162 h = __floats2bfloat162_rn(a, b);
    return *reinterpret_cast<uint32_t*>(&h);
}
#define SWZ(o) ((o) ^ (((o) >> 3) & 0x70))

#define CP16(dst, src) \
    asm volatile("cp.async.cg.shared.global [%0], [%1], 16;" :: "r"(dst), "l"(src))
#define CP_COMMIT() asm volatile("cp.async.commit_group;")
#define LDSM4(r0, r1, r2, r3, a) \
    asm volatile("ldmatrix.sync.aligned.m8n8.x4.shared.b16 {%0,%1,%2,%3}, [%4];" \
                 : "=r"(r0), "=r"(r1), "=r"(r2), "=r"(r3) : "r"(a))
#define MMA16816(d, a, b0, b1) \
    asm volatile("mma.sync.aligned.m16n8k16.row.col.f32.bf16.bf16.f32 " \
                 "{%0,%1,%2,%3}, {%4,%5,%6,%7}, {%8,%9}, {%0,%1,%2,%3};" \
                 : "+f"((d)[0]), "+f"((d)[1]), "+f"((d)[2]), "+f"((d)[3]) \
                 : "r"((a)[0]), "r"((a)[1]), "r"((a)[2]), "r"((a)[3]), \
                   "r"(b0), "r"(b1))

// ---------------- merged setup: weight transposes (z=0..2) + precompute (z=3) ---------
// z=0: W_in[768,1536] -> g_WinT ; z=1: W_x[768,784] cols 16.. -> g_WxT ; z=2: W_out
// z=3 (blockIdx.x<3): a[n] = -sum exp(A_log[n,:]), wB[n] = sum W_x[n,0:16]
__global__ void setup_all(const float* __restrict__ W_in,
                          const float* __restrict__ W_x,
                          const float* __restrict__ W_out,
                          const float* __restrict__ A_log) {
    __shared__ float t[32][33];
    int z = blockIdx.z;
    int tx = threadIdx.x, ty = threadIdx.y;
    if (z == 3) {
        if (blockIdx.x >= 3 || blockIdx.y != 0) return;
        int n = blockIdx.x * 256 + ty * 32 + tx;
        if (n < D_MODEL) {
            float s = 0.f, w = 0.f;
#pragma unroll
            for (int d = 0; d < 16; d++) s += expf(A_log[n * 16 + d]);
#pragma unroll
            for (int j = 0; j < 16; j++) w += W_x[n * 784 + j];
            g_a[n]  = -s;
            g_wB[n] = w;
        }
        return;
    }
    const float* src = (z == 0) ? W_in : (z == 1) ? W_x : W_out;
    bf16* dst        = (z == 0) ? g_WinT : (z == 1) ? g_WxT : g_WoutT;
    int ld = (z == 0) ? N1 : (z == 1) ? 784 : D_MODEL;
    int c0 = (z == 1) ? 16 : 0;
    if (z != 0 && blockIdx.x >= 24) return;    // W_x / W_out have 768 cols only

    int n0 = blockIdx.x * 32, k0 = blockIdx.y * 32;
#pragma unroll
    for (int i = 0; i < 4; i++)
        t[ty + i * 8][tx] = src[(size_t)(k0 + ty + i * 8) * ld + c0 + n0 + tx];
    __syncthreads();
#pragma unroll
    for (int i = 0; i < 4; i++)
        dst[(size_t)(n0 + ty + i * 8) * D_MODEL + k0 + tx] = __float2bfloat16(t[tx][ty + i * 8]);
}

// ---------------- K1: LayerNorm -> bf16, 192 threads, float4 ----------------
__global__ void mamba_ln(const float* __restrict__ x,
                         const float* __restrict__ gamma,
                         const float* __restrict__ beta) {
    int row = blockIdx.x;
    int t = threadIdx.x;          // 0..191
    const float4 v = ((const float4*)(x + (size_t)row * D_MODEL))[t];
    float s = v.x + v.y + v.z + v.w;
    float q = v.x * v.x + v.y * v.y + v.z * v.z + v.w * v.w;

    __shared__ float ss[6], sq[6];
#pragma unroll
    for (int o = 16; o; o >>= 1) {
        s += __shfl_down_sync(0xffffffffu, s, o);
        q += __shfl_down_sync(0xffffffffu, q, o);
    }
    if ((t & 31) == 0) { ss[t >> 5] = s; sq[t >> 5] = q; }
    __syncthreads();
    if (t == 0) {
        float S = 0.f, Q = 0.f;
#pragma unroll
        for (int i = 0; i < 6; i++) { S += ss[i]; Q += sq[i]; }
        ss[0] = S; sq[0] = Q;
    }
    __syncthreads();
    float mu  = ss[0] * (1.f / D_MODEL);
    float var = sq[0] * (1.f / D_MODEL) - mu * mu;
    float inv = rsqrtf(var + 1e-5f);
    const float4 gm = ((const float4*)gamma)[t];
    const float4 bt = ((const float4*)beta)[t];
    uint2 o;
    o.x = pk2((v.x - mu) * inv * gm.x + bt.x, (v.y - mu) * inv * gm.y + bt.y);
    o.y = pk2((v.z - mu) * inv * gm.z + bt.z, (v.w - mu) * inv * gm.w + bt.w);
    ((uint2*)(g_xn + (size_t)row * D_MODEL))[t] = o;
}

// ---------------- K3: fused conv(4)+hs, 2 tokens/block, uint4 (8 ch/thread) -----------
__global__ void mamba_convhs(const float* __restrict__ cw) {
    int pair = blockIdx.x;
    int t = threadIdx.x;              // 0..191
    int sub = t / 96;                 // token within pair
    int ct  = t % 96;                 // channel group (8 channels)
    int row = pair * 2 + sub;
    int l = row & (SEQ - 1);
    int c = ct * 8;
    const bf16* base = g_x1pre + (size_t)row * D_MODEL + c;

    float acc[8] = {0.f, 0.f, 0.f, 0.f, 0.f, 0.f, 0.f, 0.f};
#pragma unroll
    for (int k = 0; k < 4; k++) {
        int ll = l + k - 3;
        if (ll >= 0) {
            uint4 v = *(const uint4*)(base + (ptrdiff_t)(k - 3) * D_MODEL);
            const bf16* pv = (const bf16*)&v;
#pragma unroll
            for (int j = 0; j < 8; j++) {
                // cw row (c+j) is 4 contiguous floats; k-th tap
                acc[j] += cw[(c + j) * 4 + k] * __bfloat162float(pv[j]);
            }
        }
    }
    uint4 u;
    u.x = pk2(acc[0], acc[1]); u.y = pk2(acc[2], acc[3]);
    u.z = pk2(acc[4], acc[5]); u.w = pk2(acc[6], acc[7]);
    *(uint4*)(g_x1 + (size_t)row * D_MODEL + c) = u;

    float s = 0.f, d1 = 0.f, d2 = 0.f;
#pragma unroll
    for (int j = 0; j < 8; j++) {
        s  += acc[j];
        d1 += acc[j] * g_a[c + j];
        d2 += acc[j] * g_wB[c + j];
    }
    __shared__ float r0[6], r1[6], r2[6];
#pragma unroll
    for (int o = 16; o; o >>= 1) {
        s  += __shfl_down_sync(0xffffffffu, s,  o);
        d1 += __shfl_down_sync(0xffffffffu, d1, o);
        d2 += __shfl_down_sync(0xffffffffu, d2, o);
    }
    if ((t & 31) == 0) { r0[t >> 5] = s; r1[t >> 5] = d1; r2[t >> 5] = d2; }
    __syncthreads();
    // warps 0-2 cover token sub=0 (threads 0..95), warp 3 spans both (96..127)!
    // Avoid the split-warp issue: recompute ownership by thread ranges.
    if (t == 0) {
        // token 0 partials: warps 0,1,2 ; token 1 partials: warps 3,4,5
        float S  = r0[0] + r0[1] + r0[2];
        float D1 = r1[0] + r1[1] + r1[2];
        float D2 = r2[0] + r2[1] + r2[2];
        g_hs[pair * 2] = D1 + S * D2;
    }
    if (t == 96) {
        float S  = r0[3] + r0[4] + r0[5];
        float D1 = r1[3] + r1[4] + r1[5];
        float D2 = r2[3] + r2[4] + r2[5];
        g_hs[pair * 2 + 1] = D1 + S * D2;
    }
}

// ---------------- bf16 mma.sync GEMM: 128x128 CTA, 4 warps of 64x64, BK=64, 2-stage ----
// (exact R7 structure = 662us best; frag double-buffering inside k-iter)
#define BM 128
#define BN 128
#define BK 64
#define KSTEPS 12
#define STAGE_BYTES ((BM+BN)*128)       // 32768
#define SMEM_TOTAL (2*STAGE_BYTES)      // 65536

// EPI 0: A=g_xn, Bt=g_WinT : col<768 -> g_x1pre ; col>=768 -> g_sz = silu
// EPI 1: A=g_x1, Bt=g_WxT  : y=(Cm*hs + Dp*x1)*sz -> g_y
// EPI 2: A=g_y,  Bt=g_WoutT: out = acc + residual (fp32)
template <int EPI>
__global__ void __launch_bounds__(128, 2)
gemm_bf16(float* __restrict__ outp, const float* __restrict__ aux) {
    extern __shared__ char smem[];
    const uint32_t sbase = smem_u32(smem);
    const int tid = threadIdx.x, wid = tid >> 5, lane = tid & 31;
    const int wm = wid >> 1, wn = wid & 1;           // 2 x 2 warps of 64x64
    const int bm = blockIdx.y * BM, bn = blockIdx.x * BN;

    const bf16* A  = (EPI == 0) ? g_xn   : (EPI == 1) ? g_x1  : g_y;
    const bf16* Bt = (EPI == 0) ? g_WinT : (EPI == 1) ? g_WxT : g_WoutT;

    const int cr = tid >> 3;          // 0..15
    const int cc = tid & 7;           // 0..7
    const bf16* gA = A  + (size_t)(bm + cr) * D_MODEL + cc * 8;
    const bf16* gB = Bt + (size_t)(bn + cr) * D_MODEL + cc * 8;
    const uint32_t swz = SWZ(cr * 128 + cc * 16);

    float c[4][8][4];
#pragma unroll
    for (int mi = 0; mi < 4; mi++)
#pragma unroll
        for (int nj = 0; nj < 8; nj++)
#pragma unroll
            for (int e = 0; e < 4; e++) c[mi][nj][e] = 0.f;

#define LOAD_STAGE(st, k0elts)                                                   \
    {                                                                            \
        uint32_t dA = sbase + (st) * STAGE_BYTES + swz;                          \
        uint32_t dB = dA + BM * 128;                                             \
        const bf16* pA = gA + (k0elts);                                          \
        const bf16* pB = gB + (k0elts);                                          \
        _Pragma("unroll")                                                        \
        for (int i = 0; i < 8; i++) {                                            \
            CP16(dA + i * 16 * 128, pA + (size_t)i * 16 * D_MODEL);              \
            CP16(dB + i * 16 * 128, pB + (size_t)i * 16 * D_MODEL);              \
        }                                                                        \
    }

#define LOAD_FRAGS(kk, abuf, bbuf)                                               \
    {                                                                            \
        _Pragma("unroll")                                                        \
        for (int mi = 0; mi < 4; mi++) {                                         \
            int arow = wm * 64 + mi * 16 + (lane & 15);                          \
            int akb  = (kk) * 32 + ((lane >> 4) << 4);                           \
            uint32_t aad = sA + SWZ(arow * 128 + akb);                           \
            LDSM4((abuf)[mi][0], (abuf)[mi][1], (abuf)[mi][2], (abuf)[mi][3], aad); \
        }                                                                        \
        _Pragma("unroll")                                                        \
        for (int p = 0; p < 4; p++) {                                            \
            int nrow = wn * 64 + p * 16 + ((lane >> 4) << 3) + (lane & 7);       \
            int nkb  = (kk) * 32 + (((lane >> 3) & 1) << 4);                     \
            uint32_t bad = sB + SWZ(nrow * 128 + nkb);                           \
            LDSM4((bbuf)[p][0], (bbuf)[p][1], (bbuf)[p][2], (bbuf)[p][3], bad);  \
        }                                                                        \
    }

#define DO_MMAS(abuf, bbuf)                                                      \
    {                                                                            \
        _Pragma("unroll")                                                        \
        for (int mi = 0; mi < 4; mi++)                                           \
            _Pragma("unroll")                                                    \
            for (int nj = 0; nj < 8; nj++)                                       \
                MMA16816(c[mi][nj], (abuf)[mi], (bbuf)[nj >> 1][(nj & 1) * 2],   \
                         (bbuf)[nj >> 1][(nj & 1) * 2 + 1]);                     \
    }

    LOAD_STAGE(0, 0);
    CP_COMMIT();

    uint32_t a0[4][4], a1[4][4], b0[4][4], b1[4][4];

#pragma unroll 1
    for (int k = 0; k < KSTEPS; k++) {
        if (k + 1 < KSTEPS) {
            LOAD_STAGE((k + 1) & 1, (k + 1) * BK);
            CP_COMMIT();
            asm volatile("cp.async.wait_group 1;");
        } else {
            asm volatile("cp.async.wait_group 0;");
        }
        __syncthreads();

        const uint32_t sA = sbase + (k & 1) * STAGE_BYTES;
        const uint32_t sB = sA + BM * 128;

        LOAD_FRAGS(0, a0, b0);
        LOAD_FRAGS(1, a1, b1);
        DO_MMAS(a0, b0);
        LOAD_FRAGS(2, a0, b0);
        DO_MMAS(a1, b1);
        LOAD_FRAGS(3, a1, b1);
        DO_MMAS(a0, b0);
        DO_MMAS(a1, b1);
        __syncthreads();
    }

    // ---- fused epilogue straight from registers ----
#pragma unroll
    for (int mi = 0; mi < 4; mi++) {
        const int r0 = bm + wm * 64 + mi * 16 + (lane >> 2);
#pragma unroll
        for (int nj = 0; nj < 8; nj++) {
            const int gc = bn + wn * 64 + nj * 8 + ((lane & 3) << 1);
#pragma unroll
            for (int h = 0; h < 2; h++) {
                const int row = r0 + h * 8;
                const float v0 = c[mi][nj][h * 2], v1 = c[mi][nj][h * 2 + 1];
                if (EPI == 0) {
                    if (bn < D_MODEL) {
                        *(uint32_t*)(g_x1pre + (size_t)row * D_MODEL + gc) = pk2(v0, v1);
                    } else {
                        float s0 = v0 / (1.f + expf(-v0));
                        float s1 = v1 / (1.f + expf(-v1));
                        *(uint32_t*)(g_sz + (size_t)row * D_MODEL + gc - D_MODEL) = pk2(s0, s1);
                    }
                } else if (EPI == 1) {
                    size_t o = (size_t)row * D_MODEL + gc;
                    float hv = g_hs[row];
                    uint32_t xp = *(const uint32_t*)(g_x1 + o);
                    uint32_t zp = *(const uint32_t*)(g_sz + o);
                    __nv_bfloat162 xb = *(__nv_bfloat162*)&xp;
                    __nv_bfloat162 zb = *(__nv_bfloat162*)&zp;
                    float2 dp = *(const float2*)(aux + gc);
                    float y0 = (v0 * hv + dp.x * __bfloat162float(xb.x)) * __bfloat162float(zb.x);
                    float y1 = (v1 * hv + dp.y * __bfloat162float(xb.y)) * __bfloat162float(zb.y);
                    *(uint32_t*)(g_y + o) = pk2(y0, y1);
                } else {
                    size_t o = (size_t)row * D_MODEL + gc;
                    float2 rr = *(const float2*)(aux + o);
                    float2 w;
                    w.x = v0 + rr.x; w.y = v1 + rr.y;
                    *(float2*)(outp + o) = w;
                }
            }
        }
    }
#undef LOAD_STAGE
#undef LOAD_FRAGS
#undef DO_MMAS
}

// ---------------- Host launcher ----------------
extern "C" void kernel_launch(void* const* d_in, const int* in_sizes, int n_in,
                              void* d_out, int out_size) {
    const float* x      = (const float*)d_in[0];
    const float* W_in   = (const float*)d_in[1];
    const float* conv_w = (const float*)d_in[2];
    const float* W_x    = (const float*)d_in[3];
    const float* A_log  = (const float*)d_in[4];
    const float* Dp     = (const float*)d_in[5];
    const float* W_out  = (const float*)d_in[6];
    const float* gamma  = (const float*)d_in[7];
    const float* beta   = (const float*)d_in[8];
    float* out = (float*)d_out;

    cudaFuncSetAttribute(gemm_bf16<0>, cudaFuncAttributeMaxDynamicSharedMemorySize, SMEM_TOTAL);
    cudaFuncSetAttribute(gemm_bf16<1>, cudaFuncAttributeMaxDynamicSharedMemorySize, SMEM_TOTAL);
    cudaFuncSetAttribute(gemm_bf16<2>, cudaFuncAttributeMaxDynamicSharedMemorySize, SMEM_TOTAL);

    setup_all<<<dim3(N1 / 32, D_MODEL / 32, 4), dim3(32, 8)>>>(W_in, W_x, W_out, A_log);
    mamba_ln<<<TOKENS, 192>>>(x, gamma, beta);

    gemm_bf16<0><<<dim3(N1 / BN, TOKENS / BM), 128, SMEM_TOTAL>>>(nullptr, nullptr);

    mamba_convhs<<<TOKENS / 2, 192>>>(conv_w);

    gemm_bf16<1><<<dim3(D_MODEL / BN, TOKENS / BM), 128, SMEM_TOTAL>>>(nullptr, Dp);
    gemm_bf16<2><<<dim3(D_MODEL / BN, TOKENS / BM), 128, SMEM_TOTAL>>>(out, x);
}

// round 11
// speedup vs baseline: 1.4136x; 1.4136x over previous
#include <cuda_runtime.h>
#include <cuda_bf16.h>
#include <math.h>
#include <stdint.h>

typedef __nv_bfloat16 bf16;

// ---------------- Problem constants ----------------
#define D_MODEL 768
#define SEQ     4096
#define BATCH   8
#define TOKENS  (BATCH*SEQ)            // 32768
#define NELEM   (TOKENS*D_MODEL)       // 25165824
#define N1      (2*D_MODEL)            // 1536

// ---------------- Scratch (device globals; no allocation anywhere) ----------------
__device__ __align__(256) bf16 g_xn[NELEM];     // LN output (GEMM0 A)
__device__ __align__(256) bf16 g_x1pre[NELEM];  // pre-conv x1
__device__ __align__(256) bf16 g_sz[NELEM];     // silu(z)
__device__ __align__(256) bf16 g_x1[NELEM];     // post-conv x1 (GEMM1 A)
__device__ __align__(256) bf16 g_y[NELEM];      // yact (GEMM2 A)
__device__ float g_hs[TOKENS];
__device__ float g_a[D_MODEL];
__device__ float g_wB[D_MODEL];
__device__ __align__(256) bf16 g_WinT[N1*D_MODEL];       // W_in^T  [1536,768]
__device__ __align__(256) bf16 g_WxT[D_MODEL*D_MODEL];   // W_x[:,16:784]^T [768,768]
__device__ __align__(256) bf16 g_WoutT[D_MODEL*D_MODEL]; // W_out^T [768,768]

// ---------------- helpers ----------------
__device__ __forceinline__ uint32_t smem_u32(const void* p) {
    uint32_t a;
    asm("{ .reg .u64 t; cvta.to.shared.u64 t, %1; cvt.u32.u64 %0, t; }" : "=r"(a) : "l"(p));
    return a;
}
__device__ __forceinline__ uint32_t pk2(float a, float b) {
    __nv_bfloat162 h = __floats2bfloat162_rn(a, b);
    return *reinterpret_cast<uint32_t*>(&h);
}
#define SWZ(o) ((o) ^ (((o) >> 3) & 0x70))

#define CP16(dst, src) \
    asm volatile("cp.async.cg.shared.global [%0], [%1], 16;" :: "r"(dst), "l"(src))
#define CP_COMMIT() asm volatile("cp.async.commit_group;")
#define LDSM4(r0, r1, r2, r3, a) \
    asm volatile("ldmatrix.sync.aligned.m8n8.x4.shared.b16 {%0,%1,%2,%3}, [%4];" \
                 : "=r"(r0), "=r"(r1), "=r"(r2), "=r"(r3) : "r"(a))
#define MMA16816(d, a, b0, b1) \
    asm volatile("mma.sync.aligned.m16n8k16.row.col.f32.bf16.bf16.f32 " \
                 "{%0,%1,%2,%3}, {%4,%5,%6,%7}, {%8,%9}, {%0,%1,%2,%3};" \
                 : "+f"((d)[0]), "+f"((d)[1]), "+f"((d)[2]), "+f"((d)[3]) \
                 : "r"((a)[0]), "r"((a)[1]), "r"((a)[2]), "r"((a)[3]), \
                   "r"(b0), "r"(b1))

// ---------------- merged setup: weight transposes (z=0..2) + precompute (z=3) ---------
__global__ void setup_all(const float* __restrict__ W_in,
                          const float* __restrict__ W_x,
                          const float* __restrict__ W_out,
                          const float* __restrict__ A_log) {
    __shared__ float t[32][33];
    int z = blockIdx.z;
    int tx = threadIdx.x, ty = threadIdx.y;
    if (z == 3) {
        if (blockIdx.x >= 3 || blockIdx.y != 0) return;
        int n = blockIdx.x * 256 + ty * 32 + tx;
        if (n < D_MODEL) {
            float s = 0.f, w = 0.f;
#pragma unroll
            for (int d = 0; d < 16; d++) s += expf(A_log[n * 16 + d]);
#pragma unroll
            for (int j = 0; j < 16; j++) w += W_x[n * 784 + j];
            g_a[n]  = -s;
            g_wB[n] = w;
        }
        return;
    }
    const float* src = (z == 0) ? W_in : (z == 1) ? W_x : W_out;
    bf16* dst        = (z == 0) ? g_WinT : (z == 1) ? g_WxT : g_WoutT;
    int ld = (z == 0) ? N1 : (z == 1) ? 784 : D_MODEL;
    int c0 = (z == 1) ? 16 : 0;
    if (z != 0 && blockIdx.x >= 24) return;    // W_x / W_out have 768 cols only

    int n0 = blockIdx.x * 32, k0 = blockIdx.y * 32;
#pragma unroll
    for (int i = 0; i < 4; i++)
        t[ty + i * 8][tx] = src[(size_t)(k0 + ty + i * 8) * ld + c0 + n0 + tx];
    __syncthreads();
#pragma unroll
    for (int i = 0; i < 4; i++)
        dst[(size_t)(n0 + ty + i * 8) * D_MODEL + k0 + tx] = __float2bfloat16(t[tx][ty + i * 8]);
}

// ---------------- K1: LayerNorm -> bf16, 192 threads, float4 ----------------
__global__ void mamba_ln(const float* __restrict__ x,
                         const float* __restrict__ gamma,
                         const float* __restrict__ beta) {
    int row = blockIdx.x;
    int t = threadIdx.x;          // 0..191
    const float4 v = ((const float4*)(x + (size_t)row * D_MODEL))[t];
    float s = v.x + v.y + v.z + v.w;
    float q = v.x * v.x + v.y * v.y + v.z * v.z + v.w * v.w;

    __shared__ float ss[6], sq[6];
#pragma unroll
    for (int o = 16; o; o >>= 1) {
        s += __shfl_down_sync(0xffffffffu, s, o);
        q += __shfl_down_sync(0xffffffffu, q, o);
    }
    if ((t & 31) == 0) { ss[t >> 5] = s; sq[t >> 5] = q; }
    __syncthreads();
    if (t == 0) {
        float S = 0.f, Q = 0.f;
#pragma unroll
        for (int i = 0; i < 6; i++) { S += ss[i]; Q += sq[i]; }
        ss[0] = S; sq[0] = Q;
    }
    __syncthreads();
    float mu  = ss[0] * (1.f / D_MODEL);
    float var = sq[0] * (1.f / D_MODEL) - mu * mu;
    float inv = rsqrtf(var + 1e-5f);
    const float4 gm = ((const float4*)gamma)[t];
    const float4 bt = ((const float4*)beta)[t];
    uint2 o;
    o.x = pk2((v.x - mu) * inv * gm.x + bt.x, (v.y - mu) * inv * gm.y + bt.y);
    o.y = pk2((v.z - mu) * inv * gm.z + bt.z, (v.w - mu) * inv * gm.w + bt.w);
    ((uint2*)(g_xn + (size_t)row * D_MODEL))[t] = o;
}

// ---------------- K3: fused causal conv(4) + hs, vectorized bfloat162, 128 thr/row -----
// (exact R7 version — part of the 662.6us best)
__global__ void mamba_convhs(const float* __restrict__ cw) {
    int row = blockIdx.x;
    int t = threadIdx.x;          // 0..127
    int l = row & (SEQ - 1);
    const bf16* base = g_x1pre + (size_t)row * D_MODEL;
    bf16* outr = g_x1 + (size_t)row * D_MODEL;

    float s = 0.f, d1 = 0.f, d2 = 0.f;
#pragma unroll
    for (int i = 0; i < 3; i++) {
        int c2 = t + i * 128;     // pair index 0..383
        int c  = c2 * 2;
        float a0 = 0.f, a1 = 0.f;
#pragma unroll
        for (int k = 0; k < 4; k++) {
            int ll = l + k - 3;
            if (ll >= 0) {
                uint32_t vp = *(const uint32_t*)(base + (ptrdiff_t)(k - 3) * D_MODEL + c);
                __nv_bfloat162 vb = *(__nv_bfloat162*)&vp;
                a0 += cw[c * 4 + k]       * __bfloat162float(vb.x);
                a1 += cw[(c + 1) * 4 + k] * __bfloat162float(vb.y);
            }
        }
        *(uint32_t*)(outr + c) = pk2(a0, a1);
        s  += a0 + a1;
        d1 += a0 * g_a[c]  + a1 * g_a[c + 1];
        d2 += a0 * g_wB[c] + a1 * g_wB[c + 1];
    }
    __shared__ float r0[4], r1[4], r2[4];
#pragma unroll
    for (int o = 16; o; o >>= 1) {
        s  += __shfl_down_sync(0xffffffffu, s,  o);
        d1 += __shfl_down_sync(0xffffffffu, d1, o);
        d2 += __shfl_down_sync(0xffffffffu, d2, o);
    }
    if ((t & 31) == 0) { r0[t >> 5] = s; r1[t >> 5] = d1; r2[t >> 5] = d2; }
    __syncthreads();
    if (t == 0) {
        float S = r0[0] + r0[1] + r0[2] + r0[3];
        float D1 = r1[0] + r1[1] + r1[2] + r1[3];
        float D2 = r2[0] + r2[1] + r2[2] + r2[3];
        g_hs[row] = D1 + S * D2;
    }
}

// ---------------- bf16 mma.sync GEMM: 128x128 CTA, 4 warps of 64x64, BK=64, 2-stage ----
// (exact R7 structure = 662us best; frag double-buffering inside k-iter)
#define BM 128
#define BN 128
#define BK 64
#define KSTEPS 12
#define STAGE_BYTES ((BM+BN)*128)       // 32768
#define SMEM_TOTAL (2*STAGE_BYTES)      // 65536

// EPI 0: A=g_xn, Bt=g_WinT : col<768 -> g_x1pre ; col>=768 -> g_sz = silu
// EPI 1: A=g_x1, Bt=g_WxT  : y=(Cm*hs + Dp*x1)*sz -> g_y
// EPI 2: A=g_y,  Bt=g_WoutT: out = acc + residual (fp32)
template <int EPI>
__global__ void __launch_bounds__(128, 2)
gemm_bf16(float* __restrict__ outp, const float* __restrict__ aux) {
    extern __shared__ char smem[];
    const uint32_t sbase = smem_u32(smem);
    const int tid = threadIdx.x, wid = tid >> 5, lane = tid & 31;
    const int wm = wid >> 1, wn = wid & 1;           // 2 x 2 warps of 64x64
    const int bm = blockIdx.y * BM, bn = blockIdx.x * BN;

    const bf16* A  = (EPI == 0) ? g_xn   : (EPI == 1) ? g_x1  : g_y;
    const bf16* Bt = (EPI == 0) ? g_WinT : (EPI == 1) ? g_WxT : g_WoutT;

    const int cr = tid >> 3;          // 0..15
    const int cc = tid & 7;           // 0..7
    const bf16* gA = A  + (size_t)(bm + cr) * D_MODEL + cc * 8;
    const bf16* gB = Bt + (size_t)(bn + cr) * D_MODEL + cc * 8;
    const uint32_t swz = SWZ(cr * 128 + cc * 16);

    float c[4][8][4];
#pragma unroll
    for (int mi = 0; mi < 4; mi++)
#pragma unroll
        for (int nj = 0; nj < 8; nj++)
#pragma unroll
            for (int e = 0; e < 4; e++) c[mi][nj][e] = 0.f;

#define LOAD_STAGE(st, k0elts)                                                   \
    {                                                                            \
        uint32_t dA = sbase + (st) * STAGE_BYTES + swz;                          \
        uint32_t dB = dA + BM * 128;                                             \
        const bf16* pA = gA + (k0elts);                                          \
        const bf16* pB = gB + (k0elts);                                          \
        _Pragma("unroll")                                                        \
        for (int i = 0; i < 8; i++) {                                            \
            CP16(dA + i * 16 * 128, pA + (size_t)i * 16 * D_MODEL);              \
            CP16(dB + i * 16 * 128, pB + (size_t)i * 16 * D_MODEL);              \
        }                                                                        \
    }

#define LOAD_FRAGS(kk, abuf, bbuf)                                               \
    {                                                                            \
        _Pragma("unroll")                                                        \
        for (int mi = 0; mi < 4; mi++) {                                         \
            int arow = wm * 64 + mi * 16 + (lane & 15);                          \
            int akb  = (kk) * 32 + ((lane >> 4) << 4);                           \
            uint32_t aad = sA + SWZ(arow * 128 + akb);                           \
            LDSM4((abuf)[mi][0], (abuf)[mi][1], (abuf)[mi][2], (abuf)[mi][3], aad); \
        }                                                                        \
        _Pragma("unroll")                                                        \
        for (int p = 0; p < 4; p++) {                                            \
            int nrow = wn * 64 + p * 16 + ((lane >> 4) << 3) + (lane & 7);       \
            int nkb  = (kk) * 32 + (((lane >> 3) & 1) << 4);                     \
            uint32_t bad = sB + SWZ(nrow * 128 + nkb);                           \
            LDSM4((bbuf)[p][0], (bbuf)[p][1], (bbuf)[p][2], (bbuf)[p][3], bad);  \
        }                                                                        \
    }

#define DO_MMAS(abuf, bbuf)                                                      \
    {                                                                            \
        _Pragma("unroll")                                                        \
        for (int mi = 0; mi < 4; mi++)                                           \
            _Pragma("unroll")                                                    \
            for (int nj = 0; nj < 8; nj++)                                       \
                MMA16816(c[mi][nj], (abuf)[mi], (bbuf)[nj >> 1][(nj & 1) * 2],   \
                         (bbuf)[nj >> 1][(nj & 1) * 2 + 1]);                     \
    }

    LOAD_STAGE(0, 0);
    CP_COMMIT();

    uint32_t a0[4][4], a1[4][4], b0[4][4], b1[4][4];

#pragma unroll 1
    for (int k = 0; k < KSTEPS; k++) {
        if (k + 1 < KSTEPS) {
            LOAD_STAGE((k + 1) & 1, (k + 1) * BK);
            CP_COMMIT();
            asm volatile("cp.async.wait_group 1;");
        } else {
            asm volatile("cp.async.wait_group 0;");
        }
        __syncthreads();

        const uint32_t sA = sbase + (k & 1) * STAGE_BYTES;
        const uint32_t sB = sA + BM * 128;

        LOAD_FRAGS(0, a0, b0);
        LOAD_FRAGS(1, a1, b1);
        DO_MMAS(a0, b0);
        LOAD_FRAGS(2, a0, b0);
        DO_MMAS(a1, b1);
        LOAD_FRAGS(3, a1, b1);
        DO_MMAS(a0, b0);
        DO_MMAS(a1, b1);
        __syncthreads();
    }

    // ---- fused epilogue straight from registers ----
#pragma unroll
    for (int mi = 0; mi < 4; mi++) {
        const int r0 = bm + wm * 64 + mi * 16 + (lane >> 2);
#pragma unroll
        for (int nj = 0; nj < 8; nj++) {
            const int gc = bn + wn * 64 + nj * 8 + ((lane & 3) << 1);
#pragma unroll
            for (int h = 0; h < 2; h++) {
                const int row = r0 + h * 8;
                const float v0 = c[mi][nj][h * 2], v1 = c[mi][nj][h * 2 + 1];
                if (EPI == 0) {
                    if (bn < D_MODEL) {
                        *(uint32_t*)(g_x1pre + (size_t)row * D_MODEL + gc) = pk2(v0, v1);
                    } else {
                        float s0 = v0 / (1.f + expf(-v0));
                        float s1 = v1 / (1.f + expf(-v1));
                        *(uint32_t*)(g_sz + (size_t)row * D_MODEL + gc - D_MODEL) = pk2(s0, s1);
                    }
                } else if (EPI == 1) {
                    size_t o = (size_t)row * D_MODEL + gc;
                    float hv = g_hs[row];
                    uint32_t xp = *(const uint32_t*)(g_x1 + o);
                    uint32_t zp = *(const uint32_t*)(g_sz + o);
                    __nv_bfloat162 xb = *(__nv_bfloat162*)&xp;
                    __nv_bfloat162 zb = *(__nv_bfloat162*)&zp;
                    float2 dp = *(const float2*)(aux + gc);
                    float y0 = (v0 * hv + dp.x * __bfloat162float(xb.x)) * __bfloat162float(zb.x);
                    float y1 = (v1 * hv + dp.y * __bfloat162float(xb.y)) * __bfloat162float(zb.y);
                    *(uint32_t*)(g_y + o) = pk2(y0, y1);
                } else {
                    size_t o = (size_t)row * D_MODEL + gc;
                    float2 rr = *(const float2*)(aux + o);
                    float2 w;
                    w.x = v0 + rr.x; w.y = v1 + rr.y;
                    *(float2*)(outp + o) = w;
                }
            }
        }
    }
#undef LOAD_STAGE
#undef LOAD_FRAGS
#undef DO_MMAS
}

// ---------------- Host launcher ----------------
extern "C" void kernel_launch(void* const* d_in, const int* in_sizes, int n_in,
                              void* d_out, int out_size) {
    const float* x      = (const float*)d_in[0];
    const float* W_in   = (const float*)d_in[1];
    const float* conv_w = (const float*)d_in[2];
    const float* W_x    = (const float*)d_in[3];
    const float* A_log  = (const float*)d_in[4];
    const float* Dp     = (const float*)d_in[5];
    const float* W_out  = (const float*)d_in[6];
    const float* gamma  = (const float*)d_in[7];
    const float* beta   = (const float*)d_in[8];
    float* out = (float*)d_out;

    cudaFuncSetAttribute(gemm_bf16<0>, cudaFuncAttributeMaxDynamicSharedMemorySize, SMEM_TOTAL);
    cudaFuncSetAttribute(gemm_bf16<1>, cudaFuncAttributeMaxDynamicSharedMemorySize, SMEM_TOTAL);
    cudaFuncSetAttribute(gemm_bf16<2>, cudaFuncAttributeMaxDynamicSharedMemorySize, SMEM_TOTAL);

    setup_all<<<dim3(N1 / 32, D_MODEL / 32, 4), dim3(32, 8)>>>(W_in, W_x, W_out, A_log);
    mamba_ln<<<TOKENS, 192>>>(x, gamma, beta);

    gemm_bf16<0><<<dim3(N1 / BN, TOKENS / BM), 128, SMEM_TOTAL>>>(nullptr, nullptr);

    mamba_convhs<<<TOKENS, 128>>>(conv_w);

    gemm_bf16<1><<<dim3(D_MODEL / BN, TOKENS / BM), 128, SMEM_TOTAL>>>(nullptr, Dp);
    gemm_bf16<2><<<dim3(D_MODEL / BN, TOKENS / BM), 128, SMEM_TOTAL>>>(out, x);
}

// round 12
// speedup vs baseline: 1.5986x; 1.1309x over previous
#include <cuda_runtime.h>
#include <cuda_bf16.h>
#include <math.h>
#include <stdint.h>

typedef __nv_bfloat16 bf16;

// ---------------- Problem constants ----------------
#define D_MODEL 768
#define SEQ     4096
#define BATCH   8
#define TOKENS  (BATCH*SEQ)            // 32768
#define NELEM   (TOKENS*D_MODEL)       // 25165824
#define N1      (2*D_MODEL)            // 1536

// ---------------- Scratch (device globals; no allocation anywhere) ----------------
__device__ __align__(256) bf16 g_xn[NELEM];     // LN output (GEMM0 A)
__device__ __align__(256) bf16 g_x1pre[NELEM];  // pre-conv x1
__device__ __align__(256) bf16 g_sz[NELEM];     // silu(z)
__device__ __align__(256) bf16 g_x1[NELEM];     // post-conv x1 (GEMM1 A)
__device__ __align__(256) bf16 g_y[NELEM];      // yact (GEMM2 A)
__device__ float g_hs[TOKENS];
__device__ float g_a[D_MODEL];
__device__ float g_wB[D_MODEL];
__device__ uint32_t g_cwT[4 * (D_MODEL/2)];              // tap-major packed bf16x2 conv weights
__device__ __align__(256) bf16 g_WinT[N1*D_MODEL];       // W_in^T  [1536,768]
__device__ __align__(256) bf16 g_WxT[D_MODEL*D_MODEL];   // W_x[:,16:784]^T [768,768]
__device__ __align__(256) bf16 g_WoutT[D_MODEL*D_MODEL]; // W_out^T [768,768]

// ---------------- helpers ----------------
__device__ __forceinline__ uint32_t smem_u32(const void* p) {
    uint32_t a;
    asm("{ .reg .u64 t; cvta.to.shared.u64 t, %1; cvt.u32.u64 %0, t; }" : "=r"(a) : "l"(p));
    return a;
}
__device__ __forceinline__ uint32_t pk2(float a, float b) {
    __nv_bfloat162 h = __floats2bfloat162_rn(a, b);
    return *reinterpret_cast<uint32_t*>(&h);
}
__device__ __forceinline__ float2 up2(uint32_t u) {
    __nv_bfloat162 h = *reinterpret_cast<__nv_bfloat162*>(&u);
    return make_float2(__bfloat162float(h.x), __bfloat162float(h.y));
}
#define SWZ(o) ((o) ^ (((o) >> 3) & 0x70))

#define CP16(dst, src) \
    asm volatile("cp.async.cg.shared.global [%0], [%1], 16;" :: "r"(dst), "l"(src))
#define CP_COMMIT() asm volatile("cp.async.commit_group;")
#define LDSM4(r0, r1, r2, r3, a) \
    asm volatile("ldmatrix.sync.aligned.m8n8.x4.shared.b16 {%0,%1,%2,%3}, [%4];" \
                 : "=r"(r0), "=r"(r1), "=r"(r2), "=r"(r3) : "r"(a))
#define MMA16816(d, a, b0, b1) \
    asm volatile("mma.sync.aligned.m16n8k16.row.col.f32.bf16.bf16.f32 " \
                 "{%0,%1,%2,%3}, {%4,%5,%6,%7}, {%8,%9}, {%0,%1,%2,%3};" \
                 : "+f"((d)[0]), "+f"((d)[1]), "+f"((d)[2]), "+f"((d)[3]) \
                 : "r"((a)[0]), "r"((a)[1]), "r"((a)[2]), "r"((a)[3]), \
                   "r"(b0), "r"(b1))

// ---------------- merged setup: transposes (z=0..2) + precompute + cw repack (z=3) -----
__global__ void setup_all(const float* __restrict__ W_in,
                          const float* __restrict__ W_x,
                          const float* __restrict__ W_out,
                          const float* __restrict__ A_log,
                          const float* __restrict__ conv_w) {
    __shared__ float t[32][33];
    int z = blockIdx.z;
    int tx = threadIdx.x, ty = threadIdx.y;
    if (z == 3) {
        if (blockIdx.x >= 3 || blockIdx.y != 0) return;
        int n = blockIdx.x * 256 + ty * 32 + tx;
        if (n < D_MODEL) {
            float s = 0.f, w = 0.f;
#pragma unroll
            for (int d = 0; d < 16; d++) s += expf(A_log[n * 16 + d]);
#pragma unroll
            for (int j = 0; j < 16; j++) w += W_x[n * 784 + j];
            g_a[n]  = -s;
            g_wB[n] = w;
        }
        if (n < D_MODEL / 2) {
            int c = n * 2;
#pragma unroll
            for (int k = 0; k < 4; k++)
                g_cwT[k * (D_MODEL / 2) + n] = pk2(conv_w[c * 4 + k], conv_w[(c + 1) * 4 + k]);
        }
        return;
    }
    const float* src = (z == 0) ? W_in : (z == 1) ? W_x : W_out;
    bf16* dst        = (z == 0) ? g_WinT : (z == 1) ? g_WxT : g_WoutT;
    int ld = (z == 0) ? N1 : (z == 1) ? 784 : D_MODEL;
    int c0 = (z == 1) ? 16 : 0;
    if (z != 0 && blockIdx.x >= 24) return;    // W_x / W_out have 768 cols only

    int n0 = blockIdx.x * 32, k0 = blockIdx.y * 32;
#pragma unroll
    for (int i = 0; i < 4; i++)
        t[ty + i * 8][tx] = src[(size_t)(k0 + ty + i * 8) * ld + c0 + n0 + tx];
    __syncthreads();
#pragma unroll
    for (int i = 0; i < 4; i++)
        dst[(size_t)(n0 + ty + i * 8) * D_MODEL + k0 + tx] = __float2bfloat16(t[tx][ty + i * 8]);
}

// ---------------- K1: LayerNorm -> bf16, 192 threads, float4 ----------------
__global__ void mamba_ln(const float* __restrict__ x,
                         const float* __restrict__ gamma,
                         const float* __restrict__ beta) {
    int row = blockIdx.x;
    int t = threadIdx.x;          // 0..191
    const float4 v = ((const float4*)(x + (size_t)row * D_MODEL))[t];
    float s = v.x + v.y + v.z + v.w;
    float q = v.x * v.x + v.y * v.y + v.z * v.z + v.w * v.w;

    __shared__ float ss[6], sq[6];
#pragma unroll
    for (int o = 16; o; o >>= 1) {
        s += __shfl_down_sync(0xffffffffu, s, o);
        q += __shfl_down_sync(0xffffffffu, q, o);
    }
    if ((t & 31) == 0) { ss[t >> 5] = s; sq[t >> 5] = q; }
    __syncthreads();
    if (t == 0) {
        float S = 0.f, Q = 0.f;
#pragma unroll
        for (int i = 0; i < 6; i++) { S += ss[i]; Q += sq[i]; }
        ss[0] = S; sq[0] = Q;
    }
    __syncthreads();
    float mu  = ss[0] * (1.f / D_MODEL);
    float var = sq[0] * (1.f / D_MODEL) - mu * mu;
    float inv = rsqrtf(var + 1e-5f);
    const float4 gm = ((const float4*)gamma)[t];
    const float4 bt = ((const float4*)beta)[t];
    uint2 o;
    o.x = pk2((v.x - mu) * inv * gm.x + bt.x, (v.y - mu) * inv * gm.y + bt.y);
    o.y = pk2((v.z - mu) * inv * gm.z + bt.z, (v.w - mu) * inv * gm.w + bt.w);
    ((uint2*)(g_xn + (size_t)row * D_MODEL))[t] = o;
}

// ---------------- K3: conv(4)+hs, 4 tokens/block, sliding window, packed cwT ----------
// Block handles rows row0..row0+3 (one sequence). Each thread covers 3 channel pairs.
__global__ void __launch_bounds__(128)
mamba_convhs() {
    const int qb = blockIdx.x;        // 0..TOKENS/4-1
    const int row0 = qb * 4;
    const int l0 = row0 & (SEQ - 1);
    const int t = threadIdx.x;        // 0..127

    float s[4]  = {0.f, 0.f, 0.f, 0.f};
    float d1[4] = {0.f, 0.f, 0.f, 0.f};
    float d2[4] = {0.f, 0.f, 0.f, 0.f};

#pragma unroll
    for (int i = 0; i < 3; i++) {
        const int c2 = t + i * 128;   // pair index 0..383
        const int c  = c2 * 2;
        // tap weights (coalesced 4B loads)
        float2 w0 = up2(g_cwT[0 * 384 + c2]);
        float2 w1 = up2(g_cwT[1 * 384 + c2]);
        float2 w2 = up2(g_cwT[2 * 384 + c2]);
        float2 w3 = up2(g_cwT[3 * 384 + c2]);
        float2 av = *(const float2*)(g_a  + c);
        float2 wv = *(const float2*)(g_wB + c);

        const bf16* src = g_x1pre + (size_t)row0 * D_MODEL + c;
        // window win[0..3] = rows row-3..row (as float pairs)
        float2 win0, win1, win2, win3;
        win0 = (l0 >= 3) ? up2(*(const uint32_t*)(src - 3 * D_MODEL)) : make_float2(0.f, 0.f);
        win1 = (l0 >= 2) ? up2(*(const uint32_t*)(src - 2 * D_MODEL)) : make_float2(0.f, 0.f);
        win2 = (l0 >= 1) ? up2(*(const uint32_t*)(src - 1 * D_MODEL)) : make_float2(0.f, 0.f);

#pragma unroll
        for (int tok = 0; tok < 4; tok++) {
            win3 = up2(*(const uint32_t*)(src + tok * D_MODEL));
            float a0 = w0.x * win0.x + w1.x * win1.x + w2.x * win2.x + w3.x * win3.x;
            float a1 = w0.y * win0.y + w1.y * win1.y + w2.y * win2.y + w3.y * win3.y;
            *(uint32_t*)(g_x1 + (size_t)(row0 + tok) * D_MODEL + c) = pk2(a0, a1);
            s[tok]  += a0 + a1;
            d1[tok] += a0 * av.x + a1 * av.y;
            d2[tok] += a0 * wv.x + a1 * wv.y;
            win0 = win1; win1 = win2; win2 = win3;
        }
    }

    __shared__ float red[3][4][4];    // [value][warp][token]
    const int wid = t >> 5, lane = t & 31;
#pragma unroll
    for (int tok = 0; tok < 4; tok++) {
        float a = s[tok], b = d1[tok], cc = d2[tok];
#pragma unroll
        for (int o = 16; o; o >>= 1) {
            a  += __shfl_down_sync(0xffffffffu, a,  o);
            b  += __shfl_down_sync(0xffffffffu, b,  o);
            cc += __shfl_down_sync(0xffffffffu, cc, o);
        }
        if (lane == 0) { red[0][wid][tok] = a; red[1][wid][tok] = b; red[2][wid][tok] = cc; }
    }
    __syncthreads();
    if (t < 4) {
        float S  = red[0][0][t] + red[0][1][t] + red[0][2][t] + red[0][3][t];
        float D1 = red[1][0][t] + red[1][1][t] + red[1][2][t] + red[1][3][t];
        float D2 = red[2][0][t] + red[2][1][t] + red[2][2][t] + red[2][3][t];
        g_hs[row0 + t] = D1 + S * D2;
    }
}

// ---------------- bf16 mma.sync GEMM: 128x128 CTA, 4 warps of 64x64, BK=64, 2-stage ----
// (exact R7 structure = best; frag double-buffering inside k-iter)
#define BM 128
#define BN 128
#define BK 64
#define KSTEPS 12
#define STAGE_BYTES ((BM+BN)*128)       // 32768
#define SMEM_TOTAL (2*STAGE_BYTES)      // 65536

// EPI 0: A=g_xn, Bt=g_WinT : col<768 -> g_x1pre ; col>=768 -> g_sz = silu
// EPI 1: A=g_x1, Bt=g_WxT  : y=(Cm*hs + Dp*x1)*sz -> g_y
// EPI 2: A=g_y,  Bt=g_WoutT: out = acc + residual (fp32)
template <int EPI>
__global__ void __launch_bounds__(128, 2)
gemm_bf16(float* __restrict__ outp, const float* __restrict__ aux) {
    extern __shared__ char smem[];
    const uint32_t sbase = smem_u32(smem);
    const int tid = threadIdx.x, wid = tid >> 5, lane = tid & 31;
    const int wm = wid >> 1, wn = wid & 1;           // 2 x 2 warps of 64x64
    const int bm = blockIdx.y * BM, bn = blockIdx.x * BN;

    const bf16* A  = (EPI == 0) ? g_xn   : (EPI == 1) ? g_x1  : g_y;
    const bf16* Bt = (EPI == 0) ? g_WinT : (EPI == 1) ? g_WxT : g_WoutT;

    const int cr = tid >> 3;          // 0..15
    const int cc = tid & 7;           // 0..7
    const bf16* gA = A  + (size_t)(bm + cr) * D_MODEL + cc * 8;
    const bf16* gB = Bt + (size_t)(bn + cr) * D_MODEL + cc * 8;
    const uint32_t swz = SWZ(cr * 128 + cc * 16);

    float c[4][8][4];
#pragma unroll
    for (int mi = 0; mi < 4; mi++)
#pragma unroll
        for (int nj = 0; nj < 8; nj++)
#pragma unroll
            for (int e = 0; e < 4; e++) c[mi][nj][e] = 0.f;

#define LOAD_STAGE(st, k0elts)                                                   \
    {                                                                            \
        uint32_t dA = sbase + (st) * STAGE_BYTES + swz;                          \
        uint32_t dB = dA + BM * 128;                                             \
        const bf16* pA = gA + (k0elts);                                          \
        const bf16* pB = gB + (k0elts);                                          \
        _Pragma("unroll")                                                        \
        for (int i = 0; i < 8; i++) {                                            \
            CP16(dA + i * 16 * 128, pA + (size_t)i * 16 * D_MODEL);              \
            CP16(dB + i * 16 * 128, pB + (size_t)i * 16 * D_MODEL);              \
        }                                                                        \
    }

#define LOAD_FRAGS(kk, abuf, bbuf)                                               \
    {                                                                            \
        _Pragma("unroll")                                                        \
        for (int mi = 0; mi < 4; mi++) {                                         \
            int arow = wm * 64 + mi * 16 + (lane & 15);                          \
            int akb  = (kk) * 32 + ((lane >> 4) << 4);                           \
            uint32_t aad = sA + SWZ(arow * 128 + akb);                           \
            LDSM4((abuf)[mi][0], (abuf)[mi][1], (abuf)[mi][2], (abuf)[mi][3], aad); \
        }                                                                        \
        _Pragma("unroll")                                                        \
        for (int p = 0; p < 4; p++) {                                            \
            int nrow = wn * 64 + p * 16 + ((lane >> 4) << 3) + (lane & 7);       \
            int nkb  = (kk) * 32 + (((lane >> 3) & 1) << 4);                     \
            uint32_t bad = sB + SWZ(nrow * 128 + nkb);                           \
            LDSM4((bbuf)[p][0], (bbuf)[p][1], (bbuf)[p][2], (bbuf)[p][3], bad);  \
        }                                                                        \
    }

#define DO_MMAS(abuf, bbuf)                                                      \
    {                                                                            \
        _Pragma("unroll")                                                        \
        for (int mi = 0; mi < 4; mi++)                                           \
            _Pragma("unroll")                                                    \
            for (int nj = 0; nj < 8; nj++)                                       \
                MMA16816(c[mi][nj], (abuf)[mi], (bbuf)[nj >> 1][(nj & 1) * 2],   \
                         (bbuf)[nj >> 1][(nj & 1) * 2 + 1]);                     \
    }

    LOAD_STAGE(0, 0);
    CP_COMMIT();

    uint32_t a0[4][4], a1[4][4], b0[4][4], b1[4][4];

#pragma unroll 1
    for (int k = 0; k < KSTEPS; k++) {
        if (k + 1 < KSTEPS) {
            LOAD_STAGE((k + 1) & 1, (k + 1) * BK);
            CP_COMMIT();
            asm volatile("cp.async.wait_group 1;");
        } else {
            asm volatile("cp.async.wait_group 0;");
        }
        __syncthreads();

        const uint32_t sA = sbase + (k & 1) * STAGE_BYTES;
        const uint32_t sB = sA + BM * 128;

        LOAD_FRAGS(0, a0, b0);
        LOAD_FRAGS(1, a1, b1);
        DO_MMAS(a0, b0);
        LOAD_FRAGS(2, a0, b0);
        DO_MMAS(a1, b1);
        LOAD_FRAGS(3, a1, b1);
        DO_MMAS(a0, b0);
        DO_MMAS(a1, b1);
        __syncthreads();
    }

    // ---- fused epilogue straight from registers ----
#pragma unroll
    for (int mi = 0; mi < 4; mi++) {
        const int r0 = bm + wm * 64 + mi * 16 + (lane >> 2);
#pragma unroll
        for (int nj = 0; nj < 8; nj++) {
            const int gc = bn + wn * 64 + nj * 8 + ((lane & 3) << 1);
#pragma unroll
            for (int h = 0; h < 2; h++) {
                const int row = r0 + h * 8;
                const float v0 = c[mi][nj][h * 2], v1 = c[mi][nj][h * 2 + 1];
                if (EPI == 0) {
                    if (bn < D_MODEL) {
                        *(uint32_t*)(g_x1pre + (size_t)row * D_MODEL + gc) = pk2(v0, v1);
                    } else {
                        float s0 = v0 / (1.f + expf(-v0));
                        float s1 = v1 / (1.f + expf(-v1));
                        *(uint32_t*)(g_sz + (size_t)row * D_MODEL + gc - D_MODEL) = pk2(s0, s1);
                    }
                } else if (EPI == 1) {
                    size_t o = (size_t)row * D_MODEL + gc;
                    float hv = g_hs[row];
                    uint32_t xp = *(const uint32_t*)(g_x1 + o);
                    uint32_t zp = *(const uint32_t*)(g_sz + o);
                    __nv_bfloat162 xb = *(__nv_bfloat162*)&xp;
                    __nv_bfloat162 zb = *(__nv_bfloat162*)&zp;
                    float2 dp = *(const float2*)(aux + gc);
                    float y0 = (v0 * hv + dp.x * __bfloat162float(xb.x)) * __bfloat162float(zb.x);
                    float y1 = (v1 * hv + dp.y * __bfloat162float(xb.y)) * __bfloat162float(zb.y);
                    *(uint32_t*)(g_y + o) = pk2(y0, y1);
                } else {
                    size_t o = (size_t)row * D_MODEL + gc;
                    float2 rr = *(const float2*)(aux + o);
                    float2 w;
                    w.x = v0 + rr.x; w.y = v1 + rr.y;
                    *(float2*)(outp + o) = w;
                }
            }
        }
    }
#undef LOAD_STAGE
#undef LOAD_FRAGS
#undef DO_MMAS
}

// ---------------- Host launcher ----------------
extern "C" void kernel_launch(void* const* d_in, const int* in_sizes, int n_in,
                              void* d_out, int out_size) {
    const float* x      = (const float*)d_in[0];
    const float* W_in   = (const float*)d_in[1];
    const float* conv_w = (const float*)d_in[2];
    const float* W_x    = (const float*)d_in[3];
    const float* A_log  = (const float*)d_in[4];
    const float* Dp     = (const float*)d_in[5];
    const float* W_out  = (const float*)d_in[6];
    const float* gamma  = (const float*)d_in[7];
    const float* beta   = (const float*)d_in[8];
    float* out = (float*)d_out;

    cudaFuncSetAttribute(gemm_bf16<0>, cudaFuncAttributeMaxDynamicSharedMemorySize, SMEM_TOTAL);
    cudaFuncSetAttribute(gemm_bf16<1>, cudaFuncAttributeMaxDynamicSharedMemorySize, SMEM_TOTAL);
    cudaFuncSetAttribute(gemm_bf16<2>, cudaFuncAttributeMaxDynamicSharedMemorySize, SMEM_TOTAL);

    setup_all<<<dim3(N1 / 32, D_MODEL / 32, 4), dim3(32, 8)>>>(W_in, W_x, W_out, A_log, conv_w);
    mamba_ln<<<TOKENS, 192>>>(x, gamma, beta);

    gemm_bf16<0><<<dim3(N1 / BN, TOKENS / BM), 128, SMEM_TOTAL>>>(nullptr, nullptr);

    mamba_convhs<<<TOKENS / 4, 128>>>();

    gemm_bf16<1><<<dim3(D_MODEL / BN, TOKENS / BM), 128, SMEM_TOTAL>>>(nullptr, Dp);
    gemm_bf16<2><<<dim3(D_MODEL / BN, TOKENS / BM), 128, SMEM_TOTAL>>>(out, x);
}

// round 13
// speedup vs baseline: 1.6010x; 1.0015x over previous
#include <cuda_runtime.h>
#include <cuda_bf16.h>
#include <math.h>
#include <stdint.h>

typedef __nv_bfloat16 bf16;

// ---------------- Problem constants ----------------
#define D_MODEL 768
#define SEQ     4096
#define BATCH   8
#define TOKENS  (BATCH*SEQ)            // 32768
#define NELEM   (TOKENS*D_MODEL)       // 25165824
#define N1      (2*D_MODEL)            // 1536

// ---------------- Scratch (device globals; no allocation anywhere) ----------------
__device__ __align__(256) bf16 g_xn[NELEM];     // LN output (GEMM0 A)
__device__ __align__(256) bf16 g_x1pre[NELEM];  // pre-conv x1
__device__ __align__(256) bf16 g_sz[NELEM];     // silu(z)
__device__ __align__(256) bf16 g_x1[NELEM];     // post-conv x1 (GEMM1 A)
__device__ __align__(256) bf16 g_y[NELEM];      // yact (GEMM2 A)
__device__ float g_hs[TOKENS];
__device__ float g_a[D_MODEL];
__device__ float g_wB[D_MODEL];
__device__ uint32_t g_cwT[4 * (D_MODEL/2)];              // tap-major packed bf16x2 conv weights
__device__ __align__(256) bf16 g_WinT[N1*D_MODEL];       // W_in^T  [1536,768]
__device__ __align__(256) bf16 g_WxT[D_MODEL*D_MODEL];   // W_x[:,16:784]^T [768,768]
__device__ __align__(256) bf16 g_WoutT[D_MODEL*D_MODEL]; // W_out^T [768,768]

// ---------------- helpers ----------------
__device__ __forceinline__ uint32_t smem_u32(const void* p) {
    uint32_t a;
    asm("{ .reg .u64 t; cvta.to.shared.u64 t, %1; cvt.u32.u64 %0, t; }" : "=r"(a) : "l"(p));
    return a;
}
__device__ __forceinline__ uint32_t pk2(float a, float b) {
    __nv_bfloat162 h = __floats2bfloat162_rn(a, b);
    return *reinterpret_cast<uint32_t*>(&h);
}
__device__ __forceinline__ float2 up2(uint32_t u) {
    __nv_bfloat162 h = *reinterpret_cast<__nv_bfloat162*>(&u);
    return make_float2(__bfloat162float(h.x), __bfloat162float(h.y));
}
#define SWZ(o) ((o) ^ (((o) >> 3) & 0x70))

#define CP16(dst, src) \
    asm volatile("cp.async.cg.shared.global [%0], [%1], 16;" :: "r"(dst), "l"(src))
#define CP_COMMIT() asm volatile("cp.async.commit_group;")
#define LDSM4(r0, r1, r2, r3, a) \
    asm volatile("ldmatrix.sync.aligned.m8n8.x4.shared.b16 {%0,%1,%2,%3}, [%4];" \
                 : "=r"(r0), "=r"(r1), "=r"(r2), "=r"(r3) : "r"(a))
#define MMA16816(d, a, b0, b1) \
    asm volatile("mma.sync.aligned.m16n8k16.row.col.f32.bf16.bf16.f32 " \
                 "{%0,%1,%2,%3}, {%4,%5,%6,%7}, {%8,%9}, {%0,%1,%2,%3};" \
                 : "+f"((d)[0]), "+f"((d)[1]), "+f"((d)[2]), "+f"((d)[3]) \
                 : "r"((a)[0]), "r"((a)[1]), "r"((a)[2]), "r"((a)[3]), \
                   "r"(b0), "r"(b1))

// ---------------- merged setup: transposes (z=0..2) + precompute + cw repack (z=3) -----
__global__ void setup_all(const float* __restrict__ W_in,
                          const float* __restrict__ W_x,
                          const float* __restrict__ W_out,
                          const float* __restrict__ A_log,
                          const float* __restrict__ conv_w) {
    __shared__ float t[32][33];
    int z = blockIdx.z;
    int tx = threadIdx.x, ty = threadIdx.y;
    if (z == 3) {
        if (blockIdx.x >= 3 || blockIdx.y != 0) return;
        int n = blockIdx.x * 256 + ty * 32 + tx;
        if (n < D_MODEL) {
            float s = 0.f, w = 0.f;
#pragma unroll
            for (int d = 0; d < 16; d++) s += expf(A_log[n * 16 + d]);
#pragma unroll
            for (int j = 0; j < 16; j++) w += W_x[n * 784 + j];
            g_a[n]  = -s;
            g_wB[n] = w;
        }
        if (n < D_MODEL / 2) {
            int c = n * 2;
#pragma unroll
            for (int k = 0; k < 4; k++)
                g_cwT[k * (D_MODEL / 2) + n] = pk2(conv_w[c * 4 + k], conv_w[(c + 1) * 4 + k]);
        }
        return;
    }
    const float* src = (z == 0) ? W_in : (z == 1) ? W_x : W_out;
    bf16* dst        = (z == 0) ? g_WinT : (z == 1) ? g_WxT : g_WoutT;
    int ld = (z == 0) ? N1 : (z == 1) ? 784 : D_MODEL;
    int c0 = (z == 1) ? 16 : 0;
    if (z != 0 && blockIdx.x >= 24) return;    // W_x / W_out have 768 cols only

    int n0 = blockIdx.x * 32, k0 = blockIdx.y * 32;
#pragma unroll
    for (int i = 0; i < 4; i++)
        t[ty + i * 8][tx] = src[(size_t)(k0 + ty + i * 8) * ld + c0 + n0 + tx];
    __syncthreads();
#pragma unroll
    for (int i = 0; i < 4; i++)
        dst[(size_t)(n0 + ty + i * 8) * D_MODEL + k0 + tx] = __float2bfloat16(t[tx][ty + i * 8]);
}

// ---------------- K1: LayerNorm -> bf16, warp-per-row, barrier-free ----------------
__global__ void __launch_bounds__(128)
mamba_ln(const float* __restrict__ x,
         const float* __restrict__ gamma,
         const float* __restrict__ beta) {
    const int row  = blockIdx.x * 4 + (threadIdx.x >> 5);
    const int lane = threadIdx.x & 31;
    const float4* xr = (const float4*)(x + (size_t)row * D_MODEL);

    float4 v[6];
    float s = 0.f, q = 0.f;
#pragma unroll
    for (int i = 0; i < 6; i++) {
        v[i] = xr[lane + i * 32];
        s += v[i].x + v[i].y + v[i].z + v[i].w;
        q += v[i].x * v[i].x + v[i].y * v[i].y + v[i].z * v[i].z + v[i].w * v[i].w;
    }
#pragma unroll
    for (int o = 16; o; o >>= 1) {
        s += __shfl_xor_sync(0xffffffffu, s, o);
        q += __shfl_xor_sync(0xffffffffu, q, o);
    }
    const float mu  = s * (1.f / D_MODEL);
    const float var = q * (1.f / D_MODEL) - mu * mu;
    const float inv = rsqrtf(var + 1e-5f);

    uint2* orow = (uint2*)(g_xn + (size_t)row * D_MODEL);
#pragma unroll
    for (int i = 0; i < 6; i++) {
        const float4 gm = ((const float4*)gamma)[lane + i * 32];
        const float4 bt = ((const float4*)beta)[lane + i * 32];
        uint2 o;
        o.x = pk2((v[i].x - mu) * inv * gm.x + bt.x, (v[i].y - mu) * inv * gm.y + bt.y);
        o.y = pk2((v[i].z - mu) * inv * gm.z + bt.z, (v[i].w - mu) * inv * gm.w + bt.w);
        orow[lane + i * 32] = o;
    }
}

// ---------------- K3: conv(4)+hs, 8 tokens/block, sliding window, packed cwT ----------
#define CTOK 8
__global__ void __launch_bounds__(128)
mamba_convhs() {
    const int qb = blockIdx.x;        // 0..TOKENS/CTOK-1
    const int row0 = qb * CTOK;
    const int l0 = row0 & (SEQ - 1);
    const int t = threadIdx.x;        // 0..127

    float s[CTOK], d1[CTOK], d2[CTOK];
#pragma unroll
    for (int tok = 0; tok < CTOK; tok++) { s[tok] = 0.f; d1[tok] = 0.f; d2[tok] = 0.f; }

#pragma unroll
    for (int i = 0; i < 3; i++) {
        const int c2 = t + i * 128;   // pair index 0..383
        const int c  = c2 * 2;
        float2 w0 = up2(g_cwT[0 * 384 + c2]);
        float2 w1 = up2(g_cwT[1 * 384 + c2]);
        float2 w2 = up2(g_cwT[2 * 384 + c2]);
        float2 w3 = up2(g_cwT[3 * 384 + c2]);
        float2 av = *(const float2*)(g_a  + c);
        float2 wv = *(const float2*)(g_wB + c);

        const bf16* src = g_x1pre + (size_t)row0 * D_MODEL + c;
        float2 win0, win1, win2, win3;
        win0 = (l0 >= 3) ? up2(*(const uint32_t*)(src - 3 * D_MODEL)) : make_float2(0.f, 0.f);
        win1 = (l0 >= 2) ? up2(*(const uint32_t*)(src - 2 * D_MODEL)) : make_float2(0.f, 0.f);
        win2 = (l0 >= 1) ? up2(*(const uint32_t*)(src - 1 * D_MODEL)) : make_float2(0.f, 0.f);

#pragma unroll
        for (int tok = 0; tok < CTOK; tok++) {
            win3 = up2(*(const uint32_t*)(src + tok * D_MODEL));
            float a0 = w0.x * win0.x + w1.x * win1.x + w2.x * win2.x + w3.x * win3.x;
            float a1 = w0.y * win0.y + w1.y * win1.y + w2.y * win2.y + w3.y * win3.y;
            *(uint32_t*)(g_x1 + (size_t)(row0 + tok) * D_MODEL + c) = pk2(a0, a1);
            s[tok]  += a0 + a1;
            d1[tok] += a0 * av.x + a1 * av.y;
            d2[tok] += a0 * wv.x + a1 * wv.y;
            win0 = win1; win1 = win2; win2 = win3;
        }
    }

    __shared__ float red[3][4][CTOK];    // [value][warp][token]
    const int wid = t >> 5, lane = t & 31;
#pragma unroll
    for (int tok = 0; tok < CTOK; tok++) {
        float a = s[tok], b = d1[tok], cc = d2[tok];
#pragma unroll
        for (int o = 16; o; o >>= 1) {
            a  += __shfl_down_sync(0xffffffffu, a,  o);
            b  += __shfl_down_sync(0xffffffffu, b,  o);
            cc += __shfl_down_sync(0xffffffffu, cc, o);
        }
        if (lane == 0) { red[0][wid][tok] = a; red[1][wid][tok] = b; red[2][wid][tok] = cc; }
    }
    __syncthreads();
    if (t < CTOK) {
        float S  = red[0][0][t] + red[0][1][t] + red[0][2][t] + red[0][3][t];
        float D1 = red[1][0][t] + red[1][1][t] + red[1][2][t] + red[1][3][t];
        float D2 = red[2][0][t] + red[2][1][t] + red[2][2][t] + red[2][3][t];
        g_hs[row0 + t] = D1 + S * D2;
    }
}

// ---------------- bf16 mma.sync GEMM: 128x128 CTA, 4 warps of 64x64, BK=64, 2-stage ----
// (exact best structure; frag double-buffering inside k-iter)
#define BM 128
#define BN 128
#define BK 64
#define KSTEPS 12
#define STAGE_BYTES ((BM+BN)*128)       // 32768
#define SMEM_TOTAL (2*STAGE_BYTES)      // 65536

// EPI 0: A=g_xn, Bt=g_WinT : col<768 -> g_x1pre ; col>=768 -> g_sz = silu
// EPI 1: A=g_x1, Bt=g_WxT  : y=(Cm*hs + Dp*x1)*sz -> g_y
// EPI 2: A=g_y,  Bt=g_WoutT: out = acc + residual (fp32)
template <int EPI>
__global__ void __launch_bounds__(128, 2)
gemm_bf16(float* __restrict__ outp, const float* __restrict__ aux) {
    extern __shared__ char smem[];
    const uint32_t sbase = smem_u32(smem);
    const int tid = threadIdx.x, wid = tid >> 5, lane = tid & 31;
    const int wm = wid >> 1, wn = wid & 1;           // 2 x 2 warps of 64x64
    const int bm = blockIdx.y * BM, bn = blockIdx.x * BN;

    const bf16* A  = (EPI == 0) ? g_xn   : (EPI == 1) ? g_x1  : g_y;
    const bf16* Bt = (EPI == 0) ? g_WinT : (EPI == 1) ? g_WxT : g_WoutT;

    const int cr = tid >> 3;          // 0..15
    const int cc = tid & 7;           // 0..7
    const bf16* gA = A  + (size_t)(bm + cr) * D_MODEL + cc * 8;
    const bf16* gB = Bt + (size_t)(bn + cr) * D_MODEL + cc * 8;
    const uint32_t swz = SWZ(cr * 128 + cc * 16);

    float c[4][8][4];
#pragma unroll
    for (int mi = 0; mi < 4; mi++)
#pragma unroll
        for (int nj = 0; nj < 8; nj++)
#pragma unroll
            for (int e = 0; e < 4; e++) c[mi][nj][e] = 0.f;

#define LOAD_STAGE(st, k0elts)                                                   \
    {                                                                            \
        uint32_t dA = sbase + (st) * STAGE_BYTES + swz;                          \
        uint32_t dB = dA + BM * 128;                                             \
        const bf16* pA = gA + (k0elts);                                          \
        const bf16* pB = gB + (k0elts);                                          \
        _Pragma("unroll")                                                        \
        for (int i = 0; i < 8; i++) {                                            \
            CP16(dA + i * 16 * 128, pA + (size_t)i * 16 * D_MODEL);              \
            CP16(dB + i * 16 * 128, pB + (size_t)i * 16 * D_MODEL);              \
        }                                                                        \
    }

#define LOAD_FRAGS(kk, abuf, bbuf)                                               \
    {                                                                            \
        _Pragma("unroll")                                                        \
        for (int mi = 0; mi < 4; mi++) {                                         \
            int arow = wm * 64 + mi * 16 + (lane & 15);                          \
            int akb  = (kk) * 32 + ((lane >> 4) << 4);                           \
            uint32_t aad = sA + SWZ(arow * 128 + akb);                           \
            LDSM4((abuf)[mi][0], (abuf)[mi][1], (abuf)[mi][2], (abuf)[mi][3], aad); \
        }                                                                        \
        _Pragma("unroll")                                                        \
        for (int p = 0; p < 4; p++) {                                            \
            int nrow = wn * 64 + p * 16 + ((lane >> 4) << 3) + (lane & 7);       \
            int nkb  = (kk) * 32 + (((lane >> 3) & 1) << 4);                     \
            uint32_t bad = sB + SWZ(nrow * 128 + nkb);                           \
            LDSM4((bbuf)[p][0], (bbuf)[p][1], (bbuf)[p][2], (bbuf)[p][3], bad);  \
        }                                                                        \
    }

#define DO_MMAS(abuf, bbuf)                                                      \
    {                                                                            \
        _Pragma("unroll")                                                        \
        for (int mi = 0; mi < 4; mi++)                                           \
            _Pragma("unroll")                                                    \
            for (int nj = 0; nj < 8; nj++)                                       \
                MMA16816(c[mi][nj], (abuf)[mi], (bbuf)[nj >> 1][(nj & 1) * 2],   \
                         (bbuf)[nj >> 1][(nj & 1) * 2 + 1]);                     \
    }

    LOAD_STAGE(0, 0);
    CP_COMMIT();

    uint32_t a0[4][4], a1[4][4], b0[4][4], b1[4][4];

#pragma unroll 1
    for (int k = 0; k < KSTEPS; k++) {
        if (k + 1 < KSTEPS) {
            LOAD_STAGE((k + 1) & 1, (k + 1) * BK);
            CP_COMMIT();
            asm volatile("cp.async.wait_group 1;");
        } else {
            asm volatile("cp.async.wait_group 0;");
        }
        __syncthreads();

        const uint32_t sA = sbase + (k & 1) * STAGE_BYTES;
        const uint32_t sB = sA + BM * 128;

        LOAD_FRAGS(0, a0, b0);
        LOAD_FRAGS(1, a1, b1);
        DO_MMAS(a0, b0);
        LOAD_FRAGS(2, a0, b0);
        DO_MMAS(a1, b1);
        LOAD_FRAGS(3, a1, b1);
        DO_MMAS(a0, b0);
        DO_MMAS(a1, b1);
        __syncthreads();
    }

    // ---- fused epilogue straight from registers ----
#pragma unroll
    for (int mi = 0; mi < 4; mi++) {
        const int r0 = bm + wm * 64 + mi * 16 + (lane >> 2);
#pragma unroll
        for (int nj = 0; nj < 8; nj++) {
            const int gc = bn + wn * 64 + nj * 8 + ((lane & 3) << 1);
#pragma unroll
            for (int h = 0; h < 2; h++) {
                const int row = r0 + h * 8;
                const float v0 = c[mi][nj][h * 2], v1 = c[mi][nj][h * 2 + 1];
                if (EPI == 0) {
                    if (bn < D_MODEL) {
                        *(uint32_t*)(g_x1pre + (size_t)row * D_MODEL + gc) = pk2(v0, v1);
                    } else {
                        float s0 = v0 / (1.f + expf(-v0));
                        float s1 = v1 / (1.f + expf(-v1));
                        *(uint32_t*)(g_sz + (size_t)row * D_MODEL + gc - D_MODEL) = pk2(s0, s1);
                    }
                } else if (EPI == 1) {
                    size_t o = (size_t)row * D_MODEL + gc;
                    float hv = g_hs[row];
                    uint32_t xp = *(const uint32_t*)(g_x1 + o);
                    uint32_t zp = *(const uint32_t*)(g_sz + o);
                    __nv_bfloat162 xb = *(__nv_bfloat162*)&xp;
                    __nv_bfloat162 zb = *(__nv_bfloat162*)&zp;
                    float2 dp = *(const float2*)(aux + gc);
                    float y0 = (v0 * hv + dp.x * __bfloat162float(xb.x)) * __bfloat162float(zb.x);
                    float y1 = (v1 * hv + dp.y * __bfloat162float(xb.y)) * __bfloat162float(zb.y);
                    *(uint32_t*)(g_y + o) = pk2(y0, y1);
                } else {
                    size_t o = (size_t)row * D_MODEL + gc;
                    float2 rr = *(const float2*)(aux + o);
                    float2 w;
                    w.x = v0 + rr.x; w.y = v1 + rr.y;
                    *(float2*)(outp + o) = w;
                }
            }
        }
    }
#undef LOAD_STAGE
#undef LOAD_FRAGS
#undef DO_MMAS
}

// ---------------- Host launcher ----------------
extern "C" void kernel_launch(void* const* d_in, const int* in_sizes, int n_in,
                              void* d_out, int out_size) {
    const float* x      = (const float*)d_in[0];
    const float* W_in   = (const float*)d_in[1];
    const float* conv_w = (const float*)d_in[2];
    const float* W_x    = (const float*)d_in[3];
    const float* A_log  = (const float*)d_in[4];
    const float* Dp     = (const float*)d_in[5];
    const float* W_out  = (const float*)d_in[6];
    const float* gamma  = (const float*)d_in[7];
    const float* beta   = (const float*)d_in[8];
    float* out = (float*)d_out;

    cudaFuncSetAttribute(gemm_bf16<0>, cudaFuncAttributeMaxDynamicSharedMemorySize, SMEM_TOTAL);
    cudaFuncSetAttribute(gemm_bf16<1>, cudaFuncAttributeMaxDynamicSharedMemorySize, SMEM_TOTAL);
    cudaFuncSetAttribute(gemm_bf16<2>, cudaFuncAttributeMaxDynamicSharedMemorySize, SMEM_TOTAL);

    setup_all<<<dim3(N1 / 32, D_MODEL / 32, 4), dim3(32, 8)>>>(W_in, W_x, W_out, A_log, conv_w);
    mamba_ln<<<TOKENS / 4, 128>>>(x, gamma, beta);

    gemm_bf16<0><<<dim3(N1 / BN, TOKENS / BM), 128, SMEM_TOTAL>>>(nullptr, nullptr);

    mamba_convhs<<<TOKENS / CTOK, 128>>>();

    gemm_bf16<1><<<dim3(D_MODEL / BN, TOKENS / BM), 128, SMEM_TOTAL>>>(nullptr, Dp);
    gemm_bf16<2><<<dim3(D_MODEL / BN, TOKENS / BM), 128, SMEM_TOTAL>>>(out, x);
}

// round 14
// speedup vs baseline: 1.6282x; 1.0170x over previous
#include <cuda_runtime.h>
#include <cuda_bf16.h>
#include <math.h>
#include <stdint.h>

typedef __nv_bfloat16 bf16;

// ---------------- Problem constants ----------------
#define D_MODEL 768
#define SEQ     4096
#define BATCH   8
#define TOKENS  (BATCH*SEQ)            // 32768
#define NELEM   (TOKENS*D_MODEL)       // 25165824
#define N1      (2*D_MODEL)            // 1536

// ---------------- Scratch (device globals; no allocation anywhere) ----------------
__device__ __align__(256) bf16 g_xn[NELEM];     // LN output (GEMM0 A)
__device__ __align__(256) bf16 g_x1pre[NELEM];  // pre-conv x1
__device__ __align__(256) bf16 g_sz[NELEM];     // silu(z)
__device__ __align__(256) bf16 g_x1[NELEM];     // post-conv x1 (GEMM1 A)
__device__ __align__(256) bf16 g_y[NELEM];      // yact (GEMM2 A)
__device__ float g_hs[TOKENS];
__device__ float g_a[D_MODEL];
__device__ float g_wB[D_MODEL];
__device__ uint32_t g_cwT[4 * (D_MODEL/2)];              // tap-major packed bf16x2 conv weights
__device__ __align__(256) bf16 g_WinT[N1*D_MODEL];       // W_in^T  [1536,768]
__device__ __align__(256) bf16 g_WxT[D_MODEL*D_MODEL];   // W_x[:,16:784]^T [768,768]
__device__ __align__(256) bf16 g_WoutT[D_MODEL*D_MODEL]; // W_out^T [768,768]

// ---------------- helpers ----------------
__device__ __forceinline__ uint32_t smem_u32(const void* p) {
    uint32_t a;
    asm("{ .reg .u64 t; cvta.to.shared.u64 t, %1; cvt.u32.u64 %0, t; }" : "=r"(a) : "l"(p));
    return a;
}
__device__ __forceinline__ uint32_t pk2(float a, float b) {
    __nv_bfloat162 h = __floats2bfloat162_rn(a, b);
    return *reinterpret_cast<uint32_t*>(&h);
}
__device__ __forceinline__ float2 up2(uint32_t u) {
    __nv_bfloat162 h = *reinterpret_cast<__nv_bfloat162*>(&u);
    return make_float2(__bfloat162float(h.x), __bfloat162float(h.y));
}
#define SWZ(o) ((o) ^ (((o) >> 3) & 0x70))

#define CP16(dst, src) \
    asm volatile("cp.async.cg.shared.global [%0], [%1], 16;" :: "r"(dst), "l"(src))
#define CP_COMMIT() asm volatile("cp.async.commit_group;")
#define LDSM4(r0, r1, r2, r3, a) \
    asm volatile("ldmatrix.sync.aligned.m8n8.x4.shared.b16 {%0,%1,%2,%3}, [%4];" \
                 : "=r"(r0), "=r"(r1), "=r"(r2), "=r"(r3) : "r"(a))
#define MMA16816(d, a, b0, b1) \
    asm volatile("mma.sync.aligned.m16n8k16.row.col.f32.bf16.bf16.f32 " \
                 "{%0,%1,%2,%3}, {%4,%5,%6,%7}, {%8,%9}, {%0,%1,%2,%3};" \
                 : "+f"((d)[0]), "+f"((d)[1]), "+f"((d)[2]), "+f"((d)[3]) \
                 : "r"((a)[0]), "r"((a)[1]), "r"((a)[2]), "r"((a)[3]), \
                   "r"(b0), "r"(b1))

// ---------------- merged setup: transposes (z=0..2) + precompute + cw repack (z=3) -----
__global__ void setup_all(const float* __restrict__ W_in,
                          const float* __restrict__ W_x,
                          const float* __restrict__ W_out,
                          const float* __restrict__ A_log,
                          const float* __restrict__ conv_w) {
    __shared__ float t[32][33];
    int z = blockIdx.z;
    int tx = threadIdx.x, ty = threadIdx.y;
    if (z == 3) {
        if (blockIdx.x >= 3 || blockIdx.y != 0) return;
        int n = blockIdx.x * 256 + ty * 32 + tx;
        if (n < D_MODEL) {
            float s = 0.f, w = 0.f;
#pragma unroll
            for (int d = 0; d < 16; d++) s += expf(A_log[n * 16 + d]);
#pragma unroll
            for (int j = 0; j < 16; j++) w += W_x[n * 784 + j];
            g_a[n]  = -s;
            g_wB[n] = w;
        }
        if (n < D_MODEL / 2) {
            int c = n * 2;
#pragma unroll
            for (int k = 0; k < 4; k++)
                g_cwT[k * (D_MODEL / 2) + n] = pk2(conv_w[c * 4 + k], conv_w[(c + 1) * 4 + k]);
        }
        return;
    }
    const float* src = (z == 0) ? W_in : (z == 1) ? W_x : W_out;
    bf16* dst        = (z == 0) ? g_WinT : (z == 1) ? g_WxT : g_WoutT;
    int ld = (z == 0) ? N1 : (z == 1) ? 784 : D_MODEL;
    int c0 = (z == 1) ? 16 : 0;
    if (z != 0 && blockIdx.x >= 24) return;    // W_x / W_out have 768 cols only

    int n0 = blockIdx.x * 32, k0 = blockIdx.y * 32;
#pragma unroll
    for (int i = 0; i < 4; i++)
        t[ty + i * 8][tx] = src[(size_t)(k0 + ty + i * 8) * ld + c0 + n0 + tx];
    __syncthreads();
#pragma unroll
    for (int i = 0; i < 4; i++)
        dst[(size_t)(n0 + ty + i * 8) * D_MODEL + k0 + tx] = __float2bfloat16(t[tx][ty + i * 8]);
}

// ---------------- K1: LayerNorm -> bf16, warp-per-row, barrier-free ----------------
__global__ void __launch_bounds__(128)
mamba_ln(const float* __restrict__ x,
         const float* __restrict__ gamma,
         const float* __restrict__ beta) {
    const int row  = blockIdx.x * 4 + (threadIdx.x >> 5);
    const int lane = threadIdx.x & 31;
    const float4* xr = (const float4*)(x + (size_t)row * D_MODEL);

    float4 v[6];
    float s = 0.f, q = 0.f;
#pragma unroll
    for (int i = 0; i < 6; i++) {
        v[i] = xr[lane + i * 32];
        s += v[i].x + v[i].y + v[i].z + v[i].w;
        q += v[i].x * v[i].x + v[i].y * v[i].y + v[i].z * v[i].z + v[i].w * v[i].w;
    }
#pragma unroll
    for (int o = 16; o; o >>= 1) {
        s += __shfl_xor_sync(0xffffffffu, s, o);
        q += __shfl_xor_sync(0xffffffffu, q, o);
    }
    const float mu  = s * (1.f / D_MODEL);
    const float var = q * (1.f / D_MODEL) - mu * mu;
    const float inv = rsqrtf(var + 1e-5f);

    uint2* orow = (uint2*)(g_xn + (size_t)row * D_MODEL);
#pragma unroll
    for (int i = 0; i < 6; i++) {
        const float4 gm = ((const float4*)gamma)[lane + i * 32];
        const float4 bt = ((const float4*)beta)[lane + i * 32];
        uint2 o;
        o.x = pk2((v[i].x - mu) * inv * gm.x + bt.x, (v[i].y - mu) * inv * gm.y + bt.y);
        o.y = pk2((v[i].z - mu) * inv * gm.z + bt.z, (v[i].w - mu) * inv * gm.w + bt.w);
        orow[lane + i * 32] = o;
    }
}

// ---------------- K3: conv(4)+hs, 4 tokens/block, sliding window, packed cwT ----------
// (exact R11 version — measured 35.0us)
__global__ void __launch_bounds__(128)
mamba_convhs() {
    const int qb = blockIdx.x;        // 0..TOKENS/4-1
    const int row0 = qb * 4;
    const int l0 = row0 & (SEQ - 1);
    const int t = threadIdx.x;        // 0..127

    float s[4]  = {0.f, 0.f, 0.f, 0.f};
    float d1[4] = {0.f, 0.f, 0.f, 0.f};
    float d2[4] = {0.f, 0.f, 0.f, 0.f};

#pragma unroll
    for (int i = 0; i < 3; i++) {
        const int c2 = t + i * 128;   // pair index 0..383
        const int c  = c2 * 2;
        float2 w0 = up2(g_cwT[0 * 384 + c2]);
        float2 w1 = up2(g_cwT[1 * 384 + c2]);
        float2 w2 = up2(g_cwT[2 * 384 + c2]);
        float2 w3 = up2(g_cwT[3 * 384 + c2]);
        float2 av = *(const float2*)(g_a  + c);
        float2 wv = *(const float2*)(g_wB + c);

        const bf16* src = g_x1pre + (size_t)row0 * D_MODEL + c;
        float2 win0, win1, win2, win3;
        win0 = (l0 >= 3) ? up2(*(const uint32_t*)(src - 3 * D_MODEL)) : make_float2(0.f, 0.f);
        win1 = (l0 >= 2) ? up2(*(const uint32_t*)(src - 2 * D_MODEL)) : make_float2(0.f, 0.f);
        win2 = (l0 >= 1) ? up2(*(const uint32_t*)(src - 1 * D_MODEL)) : make_float2(0.f, 0.f);

#pragma unroll
        for (int tok = 0; tok < 4; tok++) {
            win3 = up2(*(const uint32_t*)(src + tok * D_MODEL));
            float a0 = w0.x * win0.x + w1.x * win1.x + w2.x * win2.x + w3.x * win3.x;
            float a1 = w0.y * win0.y + w1.y * win1.y + w2.y * win2.y + w3.y * win3.y;
            *(uint32_t*)(g_x1 + (size_t)(row0 + tok) * D_MODEL + c) = pk2(a0, a1);
            s[tok]  += a0 + a1;
            d1[tok] += a0 * av.x + a1 * av.y;
            d2[tok] += a0 * wv.x + a1 * wv.y;
            win0 = win1; win1 = win2; win2 = win3;
        }
    }

    __shared__ float red[3][4][4];    // [value][warp][token]
    const int wid = t >> 5, lane = t & 31;
#pragma unroll
    for (int tok = 0; tok < 4; tok++) {
        float a = s[tok], b = d1[tok], cc = d2[tok];
#pragma unroll
        for (int o = 16; o; o >>= 1) {
            a  += __shfl_down_sync(0xffffffffu, a,  o);
            b  += __shfl_down_sync(0xffffffffu, b,  o);
            cc += __shfl_down_sync(0xffffffffu, cc, o);
        }
        if (lane == 0) { red[0][wid][tok] = a; red[1][wid][tok] = b; red[2][wid][tok] = cc; }
    }
    __syncthreads();
    if (t < 4) {
        float S  = red[0][0][t] + red[0][1][t] + red[0][2][t] + red[0][3][t];
        float D1 = red[1][0][t] + red[1][1][t] + red[1][2][t] + red[1][3][t];
        float D2 = red[2][0][t] + red[2][1][t] + red[2][2][t] + red[2][3][t];
        g_hs[row0 + t] = D1 + S * D2;
    }
}

// ---------------- bf16 mma.sync GEMM: 128x128 CTA, 4 warps of 64x64, BK=64, 2-stage ----
// (exact best structure; frag double-buffering inside k-iter)
#define BM 128
#define BN 128
#define BK 64
#define KSTEPS 12
#define STAGE_BYTES ((BM+BN)*128)       // 32768
#define SMEM_TOTAL (2*STAGE_BYTES)      // 65536

// EPI 0: A=g_xn, Bt=g_WinT : col<768 -> g_x1pre ; col>=768 -> g_sz = silu
// EPI 1: A=g_x1, Bt=g_WxT  : y=(Cm*hs + Dp*x1)*sz -> g_y
// EPI 2: A=g_y,  Bt=g_WoutT: out = acc + residual (fp32)
template <int EPI>
__global__ void __launch_bounds__(128, 2)
gemm_bf16(float* __restrict__ outp, const float* __restrict__ aux) {
    extern __shared__ char smem[];
    const uint32_t sbase = smem_u32(smem);
    const int tid = threadIdx.x, wid = tid >> 5, lane = tid & 31;
    const int wm = wid >> 1, wn = wid & 1;           // 2 x 2 warps of 64x64
    const int bm = blockIdx.y * BM, bn = blockIdx.x * BN;

    const bf16* A  = (EPI == 0) ? g_xn   : (EPI == 1) ? g_x1  : g_y;
    const bf16* Bt = (EPI == 0) ? g_WinT : (EPI == 1) ? g_WxT : g_WoutT;

    const int cr = tid >> 3;          // 0..15
    const int cc = tid & 7;           // 0..7
    const bf16* gA = A  + (size_t)(bm + cr) * D_MODEL + cc * 8;
    const bf16* gB = Bt + (size_t)(bn + cr) * D_MODEL + cc * 8;
    const uint32_t swz = SWZ(cr * 128 + cc * 16);

    float c[4][8][4];
#pragma unroll
    for (int mi = 0; mi < 4; mi++)
#pragma unroll
        for (int nj = 0; nj < 8; nj++)
#pragma unroll
            for (int e = 0; e < 4; e++) c[mi][nj][e] = 0.f;

#define LOAD_STAGE(st, k0elts)                                                   \
    {                                                                            \
        uint32_t dA = sbase + (st) * STAGE_BYTES + swz;                          \
        uint32_t dB = dA + BM * 128;                                             \
        const bf16* pA = gA + (k0elts);                                          \
        const bf16* pB = gB + (k0elts);                                          \
        _Pragma("unroll")                                                        \
        for (int i = 0; i < 8; i++) {                                            \
            CP16(dA + i * 16 * 128, pA + (size_t)i * 16 * D_MODEL);              \
            CP16(dB + i * 16 * 128, pB + (size_t)i * 16 * D_MODEL);              \
        }                                                                        \
    }

#define LOAD_FRAGS(kk, abuf, bbuf)                                               \
    {                                                                            \
        _Pragma("unroll")                                                        \
        for (int mi = 0; mi < 4; mi++) {                                         \
            int arow = wm * 64 + mi * 16 + (lane & 15);                          \
            int akb  = (kk) * 32 + ((lane >> 4) << 4);                           \
            uint32_t aad = sA + SWZ(arow * 128 + akb);                           \
            LDSM4((abuf)[mi][0], (abuf)[mi][1], (abuf)[mi][2], (abuf)[mi][3], aad); \
        }                                                                        \
        _Pragma("unroll")                                                        \
        for (int p = 0; p < 4; p++) {                                            \
            int nrow = wn * 64 + p * 16 + ((lane >> 4) << 3) + (lane & 7);       \
            int nkb  = (kk) * 32 + (((lane >> 3) & 1) << 4);                     \
            uint32_t bad = sB + SWZ(nrow * 128 + nkb);                           \
            LDSM4((bbuf)[p][0], (bbuf)[p][1], (bbuf)[p][2], (bbuf)[p][3], bad);  \
        }                                                                        \
    }

#define DO_MMAS(abuf, bbuf)                                                      \
    {                                                                            \
        _Pragma("unroll")                                                        \
        for (int mi = 0; mi < 4; mi++)                                           \
            _Pragma("unroll")                                                    \
            for (int nj = 0; nj < 8; nj++)                                       \
                MMA16816(c[mi][nj], (abuf)[mi], (bbuf)[nj >> 1][(nj & 1) * 2],   \
                         (bbuf)[nj >> 1][(nj & 1) * 2 + 1]);                     \
    }

    LOAD_STAGE(0, 0);
    CP_COMMIT();

    uint32_t a0[4][4], a1[4][4], b0[4][4], b1[4][4];

#pragma unroll 1
    for (int k = 0; k < KSTEPS; k++) {
        if (k + 1 < KSTEPS) {
            LOAD_STAGE((k + 1) & 1, (k + 1) * BK);
            CP_COMMIT();
            asm volatile("cp.async.wait_group 1;");
        } else {
            asm volatile("cp.async.wait_group 0;");
        }
        __syncthreads();

        const uint32_t sA = sbase + (k & 1) * STAGE_BYTES;
        const uint32_t sB = sA + BM * 128;

        LOAD_FRAGS(0, a0, b0);
        LOAD_FRAGS(1, a1, b1);
        DO_MMAS(a0, b0);
        LOAD_FRAGS(2, a0, b0);
        DO_MMAS(a1, b1);
        LOAD_FRAGS(3, a1, b1);
        DO_MMAS(a0, b0);
        DO_MMAS(a1, b1);
        __syncthreads();
    }

    // ---- fused epilogue straight from registers ----
#pragma unroll
    for (int mi = 0; mi < 4; mi++) {
        const int r0 = bm + wm * 64 + mi * 16 + (lane >> 2);
#pragma unroll
        for (int nj = 0; nj < 8; nj++) {
            const int gc = bn + wn * 64 + nj * 8 + ((lane & 3) << 1);
#pragma unroll
            for (int h = 0; h < 2; h++) {
                const int row = r0 + h * 8;
                const float v0 = c[mi][nj][h * 2], v1 = c[mi][nj][h * 2 + 1];
                if (EPI == 0) {
                    if (bn < D_MODEL) {
                        *(uint32_t*)(g_x1pre + (size_t)row * D_MODEL + gc) = pk2(v0, v1);
                    } else {
                        float s0 = v0 / (1.f + expf(-v0));
                        float s1 = v1 / (1.f + expf(-v1));
                        *(uint32_t*)(g_sz + (size_t)row * D_MODEL + gc - D_MODEL) = pk2(s0, s1);
                    }
                } else if (EPI == 1) {
                    size_t o = (size_t)row * D_MODEL + gc;
                    float hv = g_hs[row];
                    uint32_t xp = *(const uint32_t*)(g_x1 + o);
                    uint32_t zp = *(const uint32_t*)(g_sz + o);
                    __nv_bfloat162 xb = *(__nv_bfloat162*)&xp;
                    __nv_bfloat162 zb = *(__nv_bfloat162*)&zp;
                    float2 dp = *(const float2*)(aux + gc);
                    float y0 = (v0 * hv + dp.x * __bfloat162float(xb.x)) * __bfloat162float(zb.x);
                    float y1 = (v1 * hv + dp.y * __bfloat162float(xb.y)) * __bfloat162float(zb.y);
                    *(uint32_t*)(g_y + o) = pk2(y0, y1);
                } else {
                    size_t o = (size_t)row * D_MODEL + gc;
                    float2 rr = *(const float2*)(aux + o);
                    float2 w;
                    w.x = v0 + rr.x; w.y = v1 + rr.y;
                    *(float2*)(outp + o) = w;
                }
            }
        }
    }
#undef LOAD_STAGE
#undef LOAD_FRAGS
#undef DO_MMAS
}

// ---------------- Host launcher ----------------
extern "C" void kernel_launch(void* const* d_in, const int* in_sizes, int n_in,
                              void* d_out, int out_size) {
    const float* x      = (const float*)d_in[0];
    const float* W_in   = (const float*)d_in[1];
    const float* conv_w = (const float*)d_in[2];
    const float* W_x    = (const float*)d_in[3];
    const float* A_log  = (const float*)d_in[4];
    const float* Dp     = (const float*)d_in[5];
    const float* W_out  = (const float*)d_in[6];
    const float* gamma  = (const float*)d_in[7];
    const float* beta   = (const float*)d_in[8];
    float* out = (float*)d_out;

    cudaFuncSetAttribute(gemm_bf16<0>, cudaFuncAttributeMaxDynamicSharedMemorySize, SMEM_TOTAL);
    cudaFuncSetAttribute(gemm_bf16<1>, cudaFuncAttributeMaxDynamicSharedMemorySize, SMEM_TOTAL);
    cudaFuncSetAttribute(gemm_bf16<2>, cudaFuncAttributeMaxDynamicSharedMemorySize, SMEM_TOTAL);

    setup_all<<<dim3(N1 / 32, D_MODEL / 32, 4), dim3(32, 8)>>>(W_in, W_x, W_out, A_log, conv_w);
    mamba_ln<<<TOKENS / 4, 128>>>(x, gamma, beta);

    gemm_bf16<0><<<dim3(N1 / BN, TOKENS / BM), 128, SMEM_TOTAL>>>(nullptr, nullptr);

    mamba_convhs<<<TOKENS / 4, 128>>>();

    gemm_bf16<1><<<dim3(D_MODEL / BN, TOKENS / BM), 128, SMEM_TOTAL>>>(nullptr, Dp);
    gemm_bf16<2><<<dim3(D_MODEL / BN, TOKENS / BM), 128, SMEM_TOTAL>>>(out, x);
}